// round 4
// baseline (speedup 1.0000x reference)
#include <cuda_runtime.h>
#include <stdint.h>

// ---------------------------------------------------------------------------
// JAX threefry2x32 (exact): 20 rounds, key schedule ks2 = k0^k1^0x1BD11BDA
// ---------------------------------------------------------------------------
__host__ __device__ __forceinline__ void threefry2x32(
    uint32_t k0, uint32_t k1, uint32_t x0, uint32_t x1,
    uint32_t& o0, uint32_t& o1)
{
    uint32_t ks2 = k0 ^ k1 ^ 0x1BD11BDAu;
    x0 += k0; x1 += k1;
#define TF_RND(R) { x0 += x1; x1 = (x1 << (R)) | (x1 >> (32 - (R))); x1 ^= x0; }
    TF_RND(13) TF_RND(15) TF_RND(26) TF_RND(6)   x0 += k1;  x1 += ks2 + 1u;
    TF_RND(17) TF_RND(29) TF_RND(16) TF_RND(24)  x0 += ks2; x1 += k0  + 2u;
    TF_RND(13) TF_RND(15) TF_RND(26) TF_RND(6)   x0 += k0;  x1 += k1  + 3u;
    TF_RND(17) TF_RND(29) TF_RND(16) TF_RND(24)  x0 += k1;  x1 += ks2 + 4u;
    TF_RND(13) TF_RND(15) TF_RND(26) TF_RND(6)   x0 += ks2; x1 += k0  + 5u;
#undef TF_RND
    o0 = x0; o1 = x1;
}

// Partitionable-threefry 32-bit random word for flat element index e (< 2^32):
// inputs (hi32(e)=0, lo32(e)=e); 32-bit output is XOR of the two halves.
__device__ __forceinline__ uint32_t tf_bits32(uint32_t k0, uint32_t k1, uint32_t e) {
    uint32_t o0, o1;
    threefry2x32(k0, k1, 0u, e, o0, o1);
    return o0 ^ o1;
}

// uniform in [0,1) from 32 random bits, exactly as jax.random.uniform
__device__ __forceinline__ float tf_uniform(uint32_t bits) {
    return __uint_as_float((bits >> 9) | 0x3F800000u) - 1.0f;
}

// ---------------------------------------------------------------------------
// Fused Linear (y = x @ W^T + b) + inverted dropout (keep=0.8, scale 1.25),
// with JAX partitionable-threefry mask bits.
//
// Block tile: 64 rows x 128 cols. 256 threads = (tx 0..31) x (ty 0..7);
// micro-tile 8 rows x 4 cols (rows ty*4..+3 and 32+ty*4..+3).
// ---------------------------------------------------------------------------
__global__ __launch_bounds__(256) void hetero_linear_dropout_kernel(
    const float* __restrict__ x, const float* __restrict__ W,
    const float* __restrict__ bias, float* __restrict__ out,
    int N, int C, uint32_t k0, uint32_t k1)
{
    __shared__ float As[64][33];     // 64 rows x 32 k, pad to 33
    __shared__ float Bs[32][132];    // 32 k x 128 n, pad to 132

    const int tid  = threadIdx.x;
    const int tx   = tid & 31;
    const int ty   = tid >> 5;
    const int base = blockIdx.x * 64;

    float acc[8][4];
#pragma unroll
    for (int i = 0; i < 8; i++)
#pragma unroll
        for (int j = 0; j < 4; j++) acc[i][j] = 0.0f;

    const int ksteps = C >> 5;
    for (int ks = 0; ks < ksteps; ks++) {
        const int kbase = ks << 5;

        // ---- load A tile: 64 rows x 32 k (512 float4, 2 per thread) ----
#pragma unroll
        for (int i = 0; i < 2; i++) {
            int idx = tid + 256 * i;          // 0..511
            int row = idx >> 3;               // 0..63
            int kq  = idx & 7;                // float4 group 0..7
            int gr  = base + row;
            float4 v = make_float4(0.f, 0.f, 0.f, 0.f);
            if (gr < N)
                v = *(const float4*)(x + (long)gr * C + kbase + kq * 4);
            As[row][kq * 4 + 0] = v.x;
            As[row][kq * 4 + 1] = v.y;
            As[row][kq * 4 + 2] = v.z;
            As[row][kq * 4 + 3] = v.w;
        }

        // ---- load B tile = W^T: 128 n x 32 k (4 float4 per thread) ----
#pragma unroll
        for (int i = 0; i < 4; i++) {
            int idx = tid + 256 * i;          // 0..1023
            int n  = idx >> 3;                // 0..127
            int kq = idx & 7;
            float4 v = *(const float4*)(W + (long)n * C + kbase + kq * 4);
            Bs[kq * 4 + 0][n] = v.x;
            Bs[kq * 4 + 1][n] = v.y;
            Bs[kq * 4 + 2][n] = v.z;
            Bs[kq * 4 + 3][n] = v.w;
        }
        __syncthreads();

        // ---- compute ----
#pragma unroll
        for (int kk = 0; kk < 32; kk++) {
            float a[8];
#pragma unroll
            for (int i = 0; i < 4; i++) {
                a[i]     = As[ty * 4 + i][kk];
                a[4 + i] = As[32 + ty * 4 + i][kk];
            }
            float4 bv = *(const float4*)&Bs[kk][tx * 4];
            float bj[4] = {bv.x, bv.y, bv.z, bv.w};
#pragma unroll
            for (int i = 0; i < 8; i++)
#pragma unroll
                for (int j = 0; j < 4; j++)
                    acc[i][j] = fmaf(a[i], bj[j], acc[i][j]);
        }
        __syncthreads();
    }

    // ---- epilogue: bias + partitionable-threefry dropout ----
    float bcol[4];
#pragma unroll
    for (int j = 0; j < 4; j++) bcol[j] = bias[tx * 4 + j];

#pragma unroll
    for (int i = 0; i < 8; i++) {
        int row = base + ((i < 4) ? (ty * 4 + i) : (32 + ty * 4 + (i - 4)));
        if (row < N) {
            uint32_t ebase = (uint32_t)row * 128u + (uint32_t)(tx * 4);
            float4 v;
            float* pv = &v.x;
#pragma unroll
            for (int j = 0; j < 4; j++) {
                float y = acc[i][j] + bcol[j];
                uint32_t bits = tf_bits32(k0, k1, ebase + (uint32_t)j);
                pv[j] = (tf_uniform(bits) < 0.8f) ? y * 1.25f : 0.0f;
            }
            *(float4*)(out + (size_t)row * 128 + tx * 4) = v;
        }
    }
}

// ---------------------------------------------------------------------------
// Launch. Inputs are interleaved per type (x_t, W_t, b_t) x 8; detect
// grouped-vs-interleaved from in_sizes[1] just in case.
// ---------------------------------------------------------------------------
static const int C_TAB[8] = {128, 256, 64, 128, 192, 96, 160, 128};

extern "C" void kernel_launch(void* const* d_in, const int* in_sizes, int n_in,
                              void* d_out, int out_size)
{
    (void)n_in; (void)out_size;
    const bool interleaved = (in_sizes[1] == 128 * C_TAB[0]);

    size_t off = 0;
    for (int t = 0; t < 8; t++) {
        const int C = C_TAB[t];
        const int xi = interleaved ? (3 * t)     : t;
        const int wi = interleaved ? (3 * t + 1) : (8 + t);
        const int bi = interleaved ? (3 * t + 2) : (16 + t);
        const int N  = in_sizes[xi] / C;

        // folded dropout key: fold_in(key(42), t) = threefry2x32([0,42],(0,t))
        uint32_t fk0, fk1;
        threefry2x32(0u, 42u, 0u, (uint32_t)t, fk0, fk1);

        const float* x = (const float*)d_in[xi];
        const float* W = (const float*)d_in[wi];
        const float* b = (const float*)d_in[bi];
        float* out = (float*)d_out + off;

        int grid = (N + 63) / 64;
        hetero_linear_dropout_kernel<<<grid, 256>>>(x, W, b, out, N, C, fk0, fk1);

        off += (size_t)N * 128;
    }
}